// round 7
// baseline (speedup 1.0000x reference)
#include <cuda_runtime.h>
#include <math.h>

#define BB 4
#define SS 1024
#define EE 512
#define HH 8
#define HD 64
#define EPSF 1e-7f
#define NROW (BB*SS)          // 4096
#define PSZ (BB*SS*EE)        // 2,097,152 floats per tensor

typedef unsigned long long ull;

// ---- f32x2 packed helpers (Blackwell FFMA2 — PTX-only path) ----
__device__ __forceinline__ ull ffma2(ull a, ull b, ull c){
  ull d; asm("fma.rn.f32x2 %0, %1, %2, %3;" : "=l"(d) : "l"(a), "l"(b), "l"(c)); return d;
}
__device__ __forceinline__ ull dup2(float x){
  ull d; asm("mov.b64 %0, {%1, %1};" : "=l"(d) : "f"(x)); return d;
}
__device__ __forceinline__ float2 unpack2(ull a){
  float2 r; asm("mov.b64 {%0, %1}, %2;" : "=f"(r.x), "=f"(r.y) : "l"(a)); return r;
}
__device__ __forceinline__ float hadd2(ull a){ float2 r = unpack2(a); return r.x + r.y; }
union F4U { float4 f; ulonglong2 u; };

// Scratch (device globals; no allocation)
__device__ float g_p[3*PSZ];          // pq, pk, pv after h_linear (projected)
__device__ float g_v[3*PSZ];          // pre-projection v = 2 zn asinh(u)
__device__ float g_vp[PSZ];           // lam_v * pv
__device__ float g_e[(size_t)BB*HH*SS*SS];  // attention weights e (134 MB)
__device__ float g_q2[BB*HH*SS];
__device__ float g_k2[BB*HH*SS];
__device__ float g_lm1[BB*HH*SS];     // lam_v - 1
__device__ float g_lam[3*NROW];       // per input row conformal factor
__device__ float g_zn[3][EE];
__device__ float g_ch[3][EE];
__device__ float g_sh[3][EE];

// ---------------------------------------------------------------------------
// Prep 1: per-column weight constants: zn = ||z[:,j]||, cosh(2r), sinh(2r)
// ---------------------------------------------------------------------------
__global__ void prep_w_kernel(const float* __restrict__ zq, const float* __restrict__ rq,
                              const float* __restrict__ zk, const float* __restrict__ rk,
                              const float* __restrict__ zv, const float* __restrict__ rv){
  const int t = blockIdx.x;
  const float* z = (t==0)?zq:((t==1)?zk:zv);
  const float* r = (t==0)?rq:((t==1)?rk:rv);
  const int j = threadIdx.x;
  float s = 0.f;
  #pragma unroll 8
  for(int n=0;n<EE;n++){ float a = z[n*EE+j]; s = fmaf(a,a,s); }
  float zn = fmaxf(sqrtf(s), EPSF);
  g_zn[t][j] = zn;
  float tr = 2.f * r[j];
  g_ch[t][j] = coshf(tr);
  g_sh[t][j] = sinhf(tr);
}

// ---------------------------------------------------------------------------
// Prep 2: lam per input row (one warp per row)
// ---------------------------------------------------------------------------
__global__ void __launch_bounds__(256) prep_lam_kernel(
    const float* __restrict__ xq, const float* __restrict__ xk, const float* __restrict__ xv){
  const int t = blockIdx.y;
  const float* __restrict__ x = (t==0)?xq:((t==1)?xk:xv);
  const int r = blockIdx.x*8 + (threadIdx.x>>5);
  const int lane = threadIdx.x & 31;
  const float4* row = (const float4*)(x + (size_t)r*EE);
  float s = 0.f;
  #pragma unroll
  for(int i=0;i<4;i++){
    float4 a = row[lane + 32*i];
    s = fmaf(a.x,a.x, fmaf(a.y,a.y, fmaf(a.z,a.z, fmaf(a.w,a.w, s))));
  }
  #pragma unroll
  for(int o=16;o>0;o>>=1) s += __shfl_xor_sync(0xffffffffu, s, o);
  if(lane==0) g_lam[t*NROW + r] = 2.f / fmaxf(1.f - s, EPSF);
}

// ---------------------------------------------------------------------------
// h_linear GEMM: v = 2*zn*asinh( lam*(x@z)/zn*cosh(2r) - (lam-1)*sinh(2r) )
// 64 rows x 128 cols per 128-thread block, 8x8 per-thread tile, FFMA2.
// ---------------------------------------------------------------------------
#define GR 64
#define GC 128
#define GK 32
__global__ void __launch_bounds__(128, 4) hgemm_kernel(
    const float* __restrict__ xq, const float* __restrict__ xk, const float* __restrict__ xv,
    const float* __restrict__ zq, const float* __restrict__ zk, const float* __restrict__ zv){
  __shared__ float4 xs4[GR*GK/4];   // [row][kq], 8 f4/row  (8 KB)
  __shared__ float4 zs4[GK*GC/4];   // [k][cq], 32 f4/k     (16 KB)
  const int t = blockIdx.z;
  const float* __restrict__ x = (t==0)?xq:((t==1)?xk:xv);
  const float* __restrict__ z = (t==0)?zq:((t==1)?zk:zv);
  const int r0 = blockIdx.x*GR, c0 = blockIdx.y*GC;
  const int tid = threadIdx.x;
  const int wy = tid>>4, wx = tid&15;

  ull accP[8][4];
  #pragma unroll
  for(int i=0;i<8;i++){
    #pragma unroll
    for(int j=0;j<4;j++) accP[i][j] = 0ull;
  }

  const float4* xg = (const float4*)x;
  const float4* zg = (const float4*)z;

  for(int k0=0;k0<EE;k0+=GK){
    __syncthreads();
    #pragma unroll
    for(int i=0;i<4;i++){
      int idx = tid + i*128; int row = idx>>3, kq = idx&7;
      xs4[idx] = xg[(size_t)(r0+row)*128 + (k0>>2) + kq];
    }
    #pragma unroll
    for(int i=0;i<8;i++){
      int idx = tid + i*128; int kk = idx>>5, cq = idx&31;
      zs4[idx] = zg[(size_t)(k0+kk)*128 + (c0>>2) + cq];
    }
    __syncthreads();
    #pragma unroll
    for(int kq=0;kq<8;kq++){
      float4 xf[8];
      #pragma unroll
      for(int i=0;i<8;i++) xf[i] = xs4[(wy*8+i)*8 + kq];
      #pragma unroll
      for(int kk=0;kk<4;kk++){
        F4U z0, z1;
        z0.f = zs4[(kq*4+kk)*32 + wx];
        z1.f = zs4[(kq*4+kk)*32 + 16 + wx];
        #pragma unroll
        for(int i=0;i<8;i++){
          float xsc = (kk==0)?xf[i].x:((kk==1)?xf[i].y:((kk==2)?xf[i].z:xf[i].w));
          ull xd = dup2(xsc);
          accP[i][0] = ffma2(xd, z0.u.x, accP[i][0]);
          accP[i][1] = ffma2(xd, z0.u.y, accP[i][1]);
          accP[i][2] = ffma2(xd, z1.u.x, accP[i][2]);
          accP[i][3] = ffma2(xd, z1.u.y, accP[i][3]);
        }
      }
    }
  }

  // epilogue: nonlinearity, write pre-projection v
  F4U znA, znB, chA, chB, shA, shB;
  znA.f = ((const float4*)g_zn[t])[(c0>>2)+wx];       znB.f = ((const float4*)g_zn[t])[(c0>>2)+16+wx];
  chA.f = ((const float4*)g_ch[t])[(c0>>2)+wx];       chB.f = ((const float4*)g_ch[t])[(c0>>2)+16+wx];
  shA.f = ((const float4*)g_sh[t])[(c0>>2)+wx];       shB.f = ((const float4*)g_sh[t])[(c0>>2)+16+wx];
  float* __restrict__ vout = g_v + (size_t)t*PSZ;
  #pragma unroll
  for(int i=0;i<8;i++){
    const int row = r0 + wy*8 + i;
    const float lam = g_lam[t*NROW + row];
    const float lm1 = lam - 1.f;
    #pragma unroll
    for(int g=0; g<2; g++){
      float2 a0 = unpack2(accP[i][2*g]);
      float2 a1 = unpack2(accP[i][2*g+1]);
      float4 zn4 = g? znB.f : znA.f;
      float4 ch4 = g? chB.f : chA.f;
      float4 sh4 = g? shB.f : shA.f;
      float4 o;
      o.x = 2.f*zn4.x*asinhf(lam*a0.x/zn4.x*ch4.x - lm1*sh4.x);
      o.y = 2.f*zn4.y*asinhf(lam*a0.y/zn4.y*ch4.y - lm1*sh4.y);
      o.z = 2.f*zn4.z*asinhf(lam*a1.x/zn4.z*ch4.z - lm1*sh4.z);
      o.w = 2.f*zn4.w*asinhf(lam*a1.y/zn4.w*ch4.w - lm1*sh4.w);
      *(float4*)(vout + (size_t)row*EE + c0 + 4*wx + 64*g) = o;
    }
  }
}

// ---------------------------------------------------------------------------
// Projection + per-head prep. One warp per row.
// ---------------------------------------------------------------------------
__global__ void __launch_bounds__(256) proj_kernel(){
  const int t = blockIdx.y;
  const int r = blockIdx.x*8 + (threadIdx.x>>5);
  const int lane = threadIdx.x & 31;
  const float4* vrow = (const float4*)(g_v + (size_t)t*PSZ + (size_t)r*EE);
  float4 vv[4]; float hs[4];
  #pragma unroll
  for(int i=0;i<4;i++){
    vv[i] = vrow[lane + 32*i];
    float p = fmaf(vv[i].x,vv[i].x, fmaf(vv[i].y,vv[i].y,
              fmaf(vv[i].z,vv[i].z, vv[i].w*vv[i].w)));
    p += __shfl_xor_sync(0xffffffffu, p, 8);
    p += __shfl_xor_sync(0xffffffffu, p, 4);
    p += __shfl_xor_sync(0xffffffffu, p, 2);
    p += __shfl_xor_sync(0xffffffffu, p, 1);
    hs[i] = p;   // head sumsq of v for head (lane>>4) + 2i
  }
  float tot = hs[0]+hs[1]+hs[2]+hs[3];
  float v2 = tot + __shfl_xor_sync(0xffffffffu, tot, 16);
  float scl = 1.f/(1.f + sqrtf(1.f + v2));
  float scl2 = scl*scl;

  float* __restrict__ pout = g_p + (size_t)t*PSZ + (size_t)r*EE;
  const int b = r >> 10, s = r & (SS-1);
  if(t < 2){
    #pragma unroll
    for(int i=0;i<4;i++){
      float4 o; o.x=vv[i].x*scl; o.y=vv[i].y*scl; o.z=vv[i].z*scl; o.w=vv[i].w*scl;
      ((float4*)pout)[lane + 32*i] = o;
      if((lane & 15) == 0){
        int h = (lane>>4) + 2*i;
        int idx = (b*HH + h)*SS + s;
        if(t==0) g_q2[idx] = hs[i]*scl2; else g_k2[idx] = hs[i]*scl2;
      }
    }
  } else {
    float* __restrict__ vpout = g_vp + (size_t)r*EE;
    #pragma unroll
    for(int i=0;i<4;i++){
      float pv2h = hs[i]*scl2;
      float lamv = 2.f / fmaxf(1.f - pv2h, EPSF);
      float4 o; o.x=vv[i].x*scl; o.y=vv[i].y*scl; o.z=vv[i].z*scl; o.w=vv[i].w*scl;
      ((float4*)pout)[lane + 32*i] = o;
      float4 w; w.x=o.x*lamv; w.y=o.y*lamv; w.z=o.z*lamv; w.w=o.w*lamv;
      ((float4*)vpout)[lane + 32*i] = w;
      if((lane & 15) == 0){
        int h = (lane>>4) + 2*i;
        g_lm1[(b*HH + h)*SS + s] = lamv - 1.f;
      }
    }
  }
}

// ---------------------------------------------------------------------------
// attn1: scores -> e, written to g_e.  Q-tile 128 x K-tile 64, 128 threads,
// 8x8 per-thread (FFMA2 packed along d).  LDS:FFMA2 balanced 1:1.
//   e = exp(-arccosh(arg)) = arg - sqrt(arg^2-1)   (division-free)
//   arg = 1 + 2*diff2 * [1/(1-q2)] * [1/(1-k2)]    (reciprocals hoisted)
// ---------------------------------------------------------------------------
#define SWZ(row, c4) ((((row)<<4)) | ((c4) ^ (((row)>>2)&15)))

__global__ void __launch_bounds__(128, 2) attn1_kernel(){
  extern __shared__ float sm[];
  float4* Qs = (float4*)sm;               // 128 x 16 f4 (32 KB)
  float4* Ks = (float4*)(sm + 128*64);    // 64 x 16 f4  (16 KB)

  const int qt = blockIdx.x, h = blockIdx.y, b = blockIdx.z;
  const int tid = threadIdx.x;
  const int ty = tid >> 3, tx = tid & 7;  // ty: 16 q-groups of 8, tx: 8 k-groups of 8
  const int q0 = qt * 128;
  const int bh = (b*HH + h)*SS;
  const float* __restrict__ pq = g_p;
  const float* __restrict__ pk = g_p + PSZ;

  #pragma unroll
  for(int i=0;i<16;i++){
    int idx = tid + i*128; int row = idx>>4, c4 = idx&15;
    Qs[SWZ(row, c4)] = *(const float4*)(pq + ((size_t)(b*SS+q0+row))*EE + h*HD + c4*4);
  }
  float q2r[8], riq[8];
  #pragma unroll
  for(int i=0;i<8;i++){
    q2r[i] = g_q2[bh + q0 + ty*8 + i];
    riq[i] = __fdividef(1.f, 1.f - q2r[i]);
  }
  float* __restrict__ eout = g_e + ((size_t)(b*HH + h))*SS*SS;

  for(int kt=0; kt<SS/64; kt++){
    const int k0 = kt*64;
    __syncthreads();
    #pragma unroll
    for(int i=0;i<8;i++){
      int idx = tid + i*128; int row = idx>>4, c4 = idx&15;
      Ks[SWZ(row, c4)] = *(const float4*)(pk + ((size_t)(b*SS+k0+row))*EE + h*HD + c4*4);
    }
    float k2r[8], rik[8];
    #pragma unroll
    for(int j=0;j<8;j++){
      k2r[j] = g_k2[bh + k0 + tx*8 + j];
      rik[j] = __fdividef(1.f, 1.f - k2r[j]);
    }
    __syncthreads();

    ull scP[8][8];
    #pragma unroll
    for(int i=0;i<8;i++){
      #pragma unroll
      for(int j=0;j<8;j++) scP[i][j] = 0ull;
    }
    #pragma unroll
    for(int kd4=0; kd4<16; kd4++){
      F4U qv[8], kv[8];
      #pragma unroll
      for(int i=0;i<8;i++) qv[i].f = Qs[SWZ(ty*8+i, kd4)];
      #pragma unroll
      for(int j=0;j<8;j++) kv[j].f = Ks[SWZ(tx*8+j, kd4)];
      #pragma unroll
      for(int i=0;i<8;i++){
        #pragma unroll
        for(int j=0;j<8;j++){
          scP[i][j] = ffma2(qv[i].u.x, kv[j].u.x, scP[i][j]);
          scP[i][j] = ffma2(qv[i].u.y, kv[j].u.y, scP[i][j]);
        }
      }
    }

    // elementwise + store e to global (plain row-major)
    #pragma unroll
    for(int i=0;i<8;i++){
      float q2 = q2r[i], ri = riq[i];
      float e8[8];
      #pragma unroll
      for(int j=0;j<8;j++){
        float sc = hadd2(scP[i][j]);
        float d2 = fmaxf(q2 + k2r[j] - 2.f*sc, 0.f);
        float t2 = 2.f * d2 * ri * rik[j];          // arg = 1 + t2
        float s  = sqrtf(t2 * (t2 + 2.f));          // sqrt(arg^2 - 1), no cancellation
        e8[j] = (1.f + t2) - s;                     // exp(-arccosh(arg))
      }
      float* erow = eout + (size_t)(q0 + ty*8 + i)*SS + k0 + tx*8;
      float4 a; a.x=e8[0]; a.y=e8[1]; a.z=e8[2]; a.w=e8[3];
      float4 c; c.x=e8[4]; c.y=e8[5]; c.z=e8[6]; c.w=e8[7];
      *(float4*)erow = a;
      *(float4*)(erow+4) = c;
    }
  }
}

// ---------------------------------------------------------------------------
// attn2: num = E @ Vp, den = E @ lm1, epilogue (midpoint + half mobius mul).
// q-tile 64, 64 threads, 8q x 8d per thread.  den computed redundantly per
// thread (scalar FFMA) so the epilogue needs no smem; m_bar norm reduced via
// 3 shuffles over the tx group.  fac = t / ((1+sqrt(1-t^2)) * mn)  [= tanh(.5 atanh t)/mn]
// ---------------------------------------------------------------------------
__global__ void __launch_bounds__(64) attn2_kernel(float* __restrict__ out){
  extern __shared__ float sm[];
  float4* Es = (float4*)sm;               // 64 x 16 f4 (16 KB)
  float4* Vs = (float4*)(sm + 64*64);     // 64 x 16 f4 (16 KB)
  float*  lm1s = sm + 2*64*64;            // 64

  const int qt = blockIdx.x, h = blockIdx.y, b = blockIdx.z;
  const int tid = threadIdx.x;
  const int ty = tid >> 3, tx = tid & 7;  // ty: 8 q-groups of 8, tx: 8 d-groups of 8
  const int q0 = qt * 64;
  const int bh = (b*HH + h)*SS;
  const float* __restrict__ esrc = g_e + ((size_t)(b*HH + h))*SS*SS;

  ull numP[8][4];
  float den[8];
  #pragma unroll
  for(int i=0;i<8;i++){
    den[i]=0.f;
    #pragma unroll
    for(int p=0;p<4;p++) numP[i][p]=0ull;
  }

  for(int kt=0; kt<SS/64; kt++){
    const int k0 = kt*64;
    __syncthreads();
    #pragma unroll
    for(int i=0;i<16;i++){
      int idx = tid + i*64; int row = idx>>4, c4 = idx&15;
      Es[SWZ(row, c4)] = *(const float4*)(esrc + (size_t)(q0+row)*SS + k0 + c4*4);
      Vs[SWZ(row, c4)] = *(const float4*)(g_vp + ((size_t)(b*SS+k0+row))*EE + h*HD + c4*4);
    }
    lm1s[tid] = g_lm1[bh + k0 + tid];
    __syncthreads();

    #pragma unroll
    for(int kk4=0; kk4<16; kk4++){
      F4U ev[8];
      #pragma unroll
      for(int i=0;i<8;i++) ev[i].f = Es[SWZ(ty*8+i, kk4)];
      F4U vv[4][2];
      #pragma unroll
      for(int r=0;r<4;r++){
        vv[r][0].f = Vs[SWZ(kk4*4+r, tx*2)];
        vv[r][1].f = Vs[SWZ(kk4*4+r, tx*2+1)];
      }
      float l0 = lm1s[kk4*4+0], l1 = lm1s[kk4*4+1];
      float l2 = lm1s[kk4*4+2], l3 = lm1s[kk4*4+3];
      #pragma unroll
      for(int i=0;i<8;i++){
        float ex = ev[i].f.x, ey = ev[i].f.y, ez = ev[i].f.z, ew = ev[i].f.w;
        ull e0 = dup2(ex), e1 = dup2(ey), e2 = dup2(ez), e3 = dup2(ew);
        numP[i][0] = ffma2(e0, vv[0][0].u.x, numP[i][0]);
        numP[i][1] = ffma2(e0, vv[0][0].u.y, numP[i][1]);
        numP[i][2] = ffma2(e0, vv[0][1].u.x, numP[i][2]);
        numP[i][3] = ffma2(e0, vv[0][1].u.y, numP[i][3]);
        numP[i][0] = ffma2(e1, vv[1][0].u.x, numP[i][0]);
        numP[i][1] = ffma2(e1, vv[1][0].u.y, numP[i][1]);
        numP[i][2] = ffma2(e1, vv[1][1].u.x, numP[i][2]);
        numP[i][3] = ffma2(e1, vv[1][1].u.y, numP[i][3]);
        numP[i][0] = ffma2(e2, vv[2][0].u.x, numP[i][0]);
        numP[i][1] = ffma2(e2, vv[2][0].u.y, numP[i][1]);
        numP[i][2] = ffma2(e2, vv[2][1].u.x, numP[i][2]);
        numP[i][3] = ffma2(e2, vv[2][1].u.y, numP[i][3]);
        numP[i][0] = ffma2(e3, vv[3][0].u.x, numP[i][0]);
        numP[i][1] = ffma2(e3, vv[3][0].u.y, numP[i][1]);
        numP[i][2] = ffma2(e3, vv[3][1].u.x, numP[i][2]);
        numP[i][3] = ffma2(e3, vv[3][1].u.y, numP[i][3]);
        den[i] = fmaf(ex, l0, den[i]);
        den[i] = fmaf(ey, l1, den[i]);
        den[i] = fmaf(ez, l2, den[i]);
        den[i] = fmaf(ew, l3, den[i]);
      }
    }
  }

  // epilogue (no smem): per thread, 8 q-rows x 8 d-cols
  #pragma unroll
  for(int i=0;i<8;i++){
    float dq = den[i];
    dq = (fabsf(dq) < EPSF) ? EPSF : dq;
    float rdq = 1.f/dq;
    float mb[8];
    float2 n0 = unpack2(numP[i][0]); float2 n1 = unpack2(numP[i][1]);
    float2 n2 = unpack2(numP[i][2]); float2 n3 = unpack2(numP[i][3]);
    mb[0]=n0.x*rdq; mb[1]=n0.y*rdq; mb[2]=n1.x*rdq; mb[3]=n1.y*rdq;
    mb[4]=n2.x*rdq; mb[5]=n2.y*rdq; mb[6]=n3.x*rdq; mb[7]=n3.y*rdq;
    float p = 0.f;
    #pragma unroll
    for(int j=0;j<8;j++) p = fmaf(mb[j], mb[j], p);
    p += __shfl_xor_sync(0xffffffffu, p, 1);
    p += __shfl_xor_sync(0xffffffffu, p, 2);
    p += __shfl_xor_sync(0xffffffffu, p, 4);   // full ||m_bar||^2 over 64 d
    float mn = fmaxf(sqrtf(p), EPSF);
    float tt = fminf(mn, 1.f - 1e-6f);
    float fac = tt / ((1.f + sqrtf(1.f - tt*tt)) * mn);  // tanh(.5*atanh(tt))/mn
    float4 oa, ob;
    oa.x=mb[0]*fac; oa.y=mb[1]*fac; oa.z=mb[2]*fac; oa.w=mb[3]*fac;
    ob.x=mb[4]*fac; ob.y=mb[5]*fac; ob.z=mb[6]*fac; ob.w=mb[7]*fac;
    float* orow = out + ((size_t)(b*SS + q0 + ty*8 + i))*EE + h*HD + tx*8;
    *(float4*)orow = oa;
    *(float4*)(orow+4) = ob;
  }
}

// ---------------------------------------------------------------------------
extern "C" void kernel_launch(void* const* d_in, const int* in_sizes, int n_in,
                              void* d_out, int out_size){
  const float* q  = (const float*)d_in[0];
  const float* k  = (const float*)d_in[1];
  const float* v  = (const float*)d_in[2];
  const float* zq = (const float*)d_in[3];
  const float* rq = (const float*)d_in[4];
  const float* zk = (const float*)d_in[5];
  const float* rk = (const float*)d_in[6];
  const float* zv = (const float*)d_in[7];
  const float* rv = (const float*)d_in[8];
  float* out = (float*)d_out;

  prep_w_kernel<<<3, EE>>>(zq, rq, zk, rk, zv, rv);
  prep_lam_kernel<<<dim3(NROW/8, 3), 256>>>(q, k, v);
  hgemm_kernel<<<dim3(NROW/GR, EE/GC, 3), 128>>>(q, k, v, zq, zk, zv);
  proj_kernel<<<dim3(NROW/8, 3), 256>>>();
  attn1_kernel<<<dim3(SS/128, HH, BB), 128, (128*64 + 64*64)*sizeof(float)>>>();
  attn2_kernel<<<dim3(SS/64, HH, BB), 64, (2*64*64 + 64)*sizeof(float)>>>(out);
}